// round 10
// baseline (speedup 1.0000x reference)
#include <cuda_runtime.h>
#include <cuda_bf16.h>
#include <math.h>
#include <stdint.h>

#define Bn   4
#define Mn   2048
#define Cn   1024
#define Hn   8
#define DQK  32
#define DV   128
#define ROWS (Bn*Mn)
#define SLOPE 0.2f
#define QSCALE 0.25503695218998236f  // (1/sqrt(32))*log2(e)

#if defined(__CUDA_ARCH__) && (defined(__CUDA_ARCH_FEAT_SM103_ALL) || defined(__CUDA_ARCH_FEAT_SM100_ALL))
#define HAS_TC 1
#else
#define HAS_TC 0
#endif

__device__ __nv_bfloat16 g_Xb[ROWS * Cn];
__device__ __nv_bfloat16 g_Yb[ROWS * Cn];
__device__ __nv_bfloat16 g_Wqb[Cn * 256];
__device__ __nv_bfloat16 g_Wkb[Cn * 256];
__device__ __nv_bfloat16 g_Wvb[Cn * Cn];
__device__ __nv_bfloat16 g_Q[ROWS * 256];
__device__ __nv_bfloat16 g_K[ROWS * 256];
__device__ __nv_bfloat16 g_V[ROWS * 1024];
__device__ __nv_bfloat16 g_Vt0[DV * Mn];   // diagnostic Vt for (b=0,h=0): [dv][m]

// ---------------- helpers ----------------
__device__ __forceinline__ uint32_t smem_u32(const void* p) {
    return (uint32_t)__cvta_generic_to_shared(p);
}
__device__ __forceinline__ uint32_t pack_bf16(float lo, float hi) {
    uint32_t r;
    asm("cvt.rn.bf16x2.f32 %0, %1, %2;" : "=r"(r) : "f"(hi), "f"(lo));
    return r;
}
__device__ __forceinline__ float ex2(float x) {
    float r; asm("ex2.approx.f32 %0, %1;" : "=f"(r) : "f"(x)); return r;
}
__device__ __forceinline__ void ldsm_x4(uint32_t a, uint32_t& r0, uint32_t& r1,
                                        uint32_t& r2, uint32_t& r3) {
    asm volatile("ldmatrix.sync.aligned.m8n8.x4.shared.b16 {%0,%1,%2,%3}, [%4];"
                 : "=r"(r0), "=r"(r1), "=r"(r2), "=r"(r3) : "r"(a));
}
__device__ __forceinline__ void ldsm_x4_t(uint32_t a, uint32_t& r0, uint32_t& r1,
                                          uint32_t& r2, uint32_t& r3) {
    asm volatile("ldmatrix.sync.aligned.m8n8.x4.trans.shared.b16 {%0,%1,%2,%3}, [%4];"
                 : "=r"(r0), "=r"(r1), "=r"(r2), "=r"(r3) : "r"(a));
}
__device__ __forceinline__ void mma16816(float* c, const uint32_t* a, uint32_t b0, uint32_t b1) {
    asm volatile(
        "mma.sync.aligned.m16n8k16.row.col.f32.bf16.bf16.f32 "
        "{%0,%1,%2,%3}, {%4,%5,%6,%7}, {%8,%9}, {%0,%1,%2,%3};"
        : "+f"(c[0]), "+f"(c[1]), "+f"(c[2]), "+f"(c[3])
        : "r"(a[0]), "r"(a[1]), "r"(a[2]), "r"(a[3]), "r"(b0), "r"(b1));
}
__device__ __forceinline__ void cp16(void* dst, const void* src) {
    asm volatile("cp.async.cg.shared.global [%0], [%1], 16;"
                 :: "r"(smem_u32(dst)), "l"(src) : "memory");
}
__device__ __forceinline__ void cp_commit() {
    asm volatile("cp.async.commit_group;" ::: "memory");
}
template <int N>
__device__ __forceinline__ void cp_wait() {
    asm volatile("cp.async.wait_group %0;" :: "n"(N) : "memory");
}

// ---------------- tcgen05 primitives ----------------
__device__ __forceinline__ uint32_t elect_one_pred() {
    uint32_t pred;
    asm volatile(
        "{\n\t.reg .pred p;\n\telect.sync _|p, 0xFFFFFFFF;\n\tselp.b32 %0, 1, 0, p;\n\t}"
        : "=r"(pred));
    return pred;
}
#define TCG_ALLOC(sa, n) \
    asm volatile("tcgen05.alloc.cta_group::1.sync.aligned.shared::cta.b32 [%0], %1;" \
                 :: "r"(sa), "r"(n) : "memory")
#define TCG_DEALLOC(t, n) \
    asm volatile("tcgen05.dealloc.cta_group::1.sync.aligned.b32 %0, %1;" :: "r"(t), "r"(n))
#define TCG_COMMIT(mb) \
    asm volatile("tcgen05.commit.cta_group::1.mbarrier::arrive::one.shared::cluster.b64 [%0];" \
                 :: "r"(mb) : "memory")
#define TCG_WAIT_LD()  asm volatile("tcgen05.wait::ld.sync.aligned;" ::: "memory")
#define TCG_WAIT_ST()  asm volatile("tcgen05.wait::st.sync.aligned;" ::: "memory")
#define TCG_FENCE_B()  asm volatile("tcgen05.fence::before_thread_sync;" ::: "memory")
#define TCG_FENCE_A()  asm volatile("tcgen05.fence::after_thread_sync;" ::: "memory")
#define FENCE_ASYNC()  asm volatile("fence.proxy.async.shared::cta;" ::: "memory")
#define MBAR_INIT(mb, cnt) \
    asm volatile("mbarrier.init.shared.b64 [%0], %1;" :: "r"(mb), "r"(cnt) : "memory")
#define MBAR_WAIT(mb, par) do { \
    uint32_t _mb = (mb), _p = (par), _d; \
    asm volatile("{\n\t.reg .pred p;\n\t" \
        "mbarrier.try_wait.parity.acquire.cta.shared::cta.b64 p, [%1], %2;\n\t" \
        "selp.b32 %0, 1, 0, p;\n\t}" : "=r"(_d) : "r"(_mb), "r"(_p) : "memory"); \
    if (!_d) { \
        asm volatile("{\n\t.reg .pred P1;\n\t" \
            "WL_%=:\n\t" \
            "mbarrier.try_wait.parity.acquire.cta.shared::cta.b64 P1, [%0], %1, 0x989680;\n\t" \
            "@P1 bra.uni WD_%=;\n\tbra.uni WL_%=;\n\tWD_%=:\n\t}" \
            :: "r"(_mb), "r"(_p) : "memory"); \
    } \
} while (0)

#define TCG_LD_X32(r, ta) \
    asm volatile("tcgen05.ld.sync.aligned.32x32b.x32.b32 " \
        "{%0,%1,%2,%3,%4,%5,%6,%7,%8,%9,%10,%11,%12,%13,%14,%15," \
        "%16,%17,%18,%19,%20,%21,%22,%23,%24,%25,%26,%27,%28,%29,%30,%31}, [%32];" \
        : "=r"((r)[0]), "=r"((r)[1]), "=r"((r)[2]), "=r"((r)[3]), \
          "=r"((r)[4]), "=r"((r)[5]), "=r"((r)[6]), "=r"((r)[7]), \
          "=r"((r)[8]), "=r"((r)[9]), "=r"((r)[10]), "=r"((r)[11]), \
          "=r"((r)[12]), "=r"((r)[13]), "=r"((r)[14]), "=r"((r)[15]), \
          "=r"((r)[16]), "=r"((r)[17]), "=r"((r)[18]), "=r"((r)[19]), \
          "=r"((r)[20]), "=r"((r)[21]), "=r"((r)[22]), "=r"((r)[23]), \
          "=r"((r)[24]), "=r"((r)[25]), "=r"((r)[26]), "=r"((r)[27]), \
          "=r"((r)[28]), "=r"((r)[29]), "=r"((r)[30]), "=r"((r)[31]) \
        : "r"(ta))
#define TCG_ST_X16(ta, r) \
    asm volatile("tcgen05.st.sync.aligned.32x32b.x16.b32 [%0], " \
        "{%1,%2,%3,%4,%5,%6,%7,%8,%9,%10,%11,%12,%13,%14,%15,%16};" \
        :: "r"(ta), \
           "r"((r)[0]),  "r"((r)[1]),  "r"((r)[2]),  "r"((r)[3]), \
           "r"((r)[4]),  "r"((r)[5]),  "r"((r)[6]),  "r"((r)[7]), \
           "r"((r)[8]),  "r"((r)[9]),  "r"((r)[10]), "r"((r)[11]), \
           "r"((r)[12]), "r"((r)[13]), "r"((r)[14]), "r"((r)[15]) \
        : "memory")

#if HAS_TC
__device__ __forceinline__ void mma_f16_ts(uint32_t d, uint32_t a, uint64_t bd,
                                           uint32_t idesc, bool en) {
    uint32_t e = en ? 1u : 0u;
    asm volatile(
        "{\n\t.reg .pred p;\n\tsetp.ne.u32 p, %5, 0;\n\t"
        "tcgen05.mma.cta_group::1.kind::f16 [%0], [%1], %2, %3, {%4,%4,%4,%4}, p;\n\t}"
        :: "r"(d), "r"(a), "l"(bd), "r"(idesc), "r"(0u), "r"(e) : "memory");
}
#endif
__device__ __forceinline__ uint64_t desc_k(uint32_t addr) {
    const uint64_t base = (2ull << 61) | (1ull << 46) | (64ull << 32) | (1ull << 16);
    return base | ((uint64_t)(addr >> 4) & 0x3FFF);
}

// ---------------- fp32 -> bf16 convert (4 float4 per thread) ----------------
__global__ void __launch_bounds__(256) cvt_all(
    const float* __restrict__ x, const float* __restrict__ y,
    const float* __restrict__ wq, const float* __restrict__ wk,
    const float* __restrict__ wv)
{
    int bid = blockIdx.x;
    const float* src;
    __nv_bfloat16* dst;
    int base;
    if (bid < 2048)      { src = x;  dst = g_Xb;  base = bid; }
    else if (bid < 4096) { src = y;  dst = g_Yb;  base = bid - 2048; }
    else if (bid < 4160) { src = wq; dst = g_Wqb; base = bid - 4096; }
    else if (bid < 4224) { src = wk; dst = g_Wkb; base = bid - 4160; }
    else                 { src = wv; dst = g_Wvb; base = bid - 4224; }
    #pragma unroll
    for (int i = 0; i < 4; i++) {
        size_t off = (size_t)base * 4096 + i * 1024 + threadIdx.x * 4;
        float4 f = *(const float4*)(src + off);
        uint2 u;
        u.x = pack_bf16(f.x, f.y);
        u.y = pack_bf16(f.z, f.w);
        *(uint2*)(dst + off) = u;
    }
}

// ---------------- diagnostic: Vt for (b=0,h=0): g_Vt0[dv][m] ----------------
__global__ void __launch_bounds__(256) mk_vt0()
{
    int t = blockIdx.x;   // 16 blocks, 128 m-rows each
    for (int i = threadIdx.x; i < 16384; i += 256) {
        int dv = i & 127, ml = i >> 7;
        g_Vt0[(size_t)dv * Mn + t * 128 + ml] =
            g_V[(size_t)(t * 128 + ml) * 1024 + dv];
    }
}

// ---------------- fused projection GEMM (exact R3 version) ----------------
__global__ void __launch_bounds__(256) gemm_fused(
    const float* __restrict__ bq, const float* __restrict__ bk,
    const float* __restrict__ bv)
{
    extern __shared__ char smem[];
    auto Ast = [&](int s) { return (__nv_bfloat16(*)[72])(smem + s * 35840); };
    auto Wst = [&](int s) { return (__nv_bfloat16(*)[136])(smem + s * 35840 + 18432); };

    const int tid  = threadIdx.x;
    const int lane = tid & 31;
    const int warp = tid >> 5;
    const int wm   = warp >> 1;
    const int wn   = warp & 1;

    int bid = blockIdx.x;
    const __nv_bfloat16 *A, *W;
    const float* bias;
    __nv_bfloat16* out;
    int N, bx, by;
    float oscale;
    if (bid < 128)      { A = g_Xb; W = g_Wqb; bias = bq; out = g_Q; N = 256;
                          bx = bid & 1;  by = bid >> 1; oscale = QSCALE; }
    else if (bid < 256) { bid -= 128; A = g_Yb; W = g_Wkb; bias = bk; out = g_K; N = 256;
                          bx = bid & 1;  by = bid >> 1; oscale = 1.f; }
    else                { bid -= 256; A = g_Yb; W = g_Wvb; bias = bv; out = g_V; N = 1024;
                          bx = bid & 7;  by = bid >> 3; oscale = 1.f; }
    const int m0 = by * 128;
    const int n0 = bx * 128;

    auto loadTile = [&](int s, int it) {
        __nv_bfloat16 (*Ad)[72]  = Ast(s);
        __nv_bfloat16 (*Wd)[136] = Wst(s);
        #pragma unroll
        for (int i = 0; i < 4; i++) {
            int idx = tid + i * 256;
            int r = idx >> 3, c = idx & 7;
            cp16(&Ad[r][c * 8], A + (size_t)(m0 + r) * 1024 + it * 64 + c * 8);
        }
        #pragma unroll
        for (int i = 0; i < 4; i++) {
            int idx = tid + i * 256;
            int r = idx >> 4, c = idx & 15;
            cp16(&Wd[r][c * 8], W + (size_t)(it * 64 + r) * N + n0 + c * 8);
        }
        cp_commit();
    };

    float acc[2][8][4] = {};
    loadTile(0, 0);
    loadTile(1, 1);

    for (int it = 0; it < 16; it++) {
        if (it < 15) cp_wait<1>(); else cp_wait<0>();
        __syncthreads();
        __nv_bfloat16 (*Ab)[72]  = Ast(it % 3);
        __nv_bfloat16 (*Wb)[136] = Wst(it % 3);
        #pragma unroll
        for (int ks = 0; ks < 4; ks++) {
            uint32_t afr[2][4];
            #pragma unroll
            for (int mt = 0; mt < 2; mt++) {
                int row = wm * 32 + mt * 16 + ((lane >> 3) & 1) * 8 + (lane & 7);
                int col = ks * 16 + (lane >> 4) * 8;
                ldsm_x4(smem_u32(&Ab[row][col]), afr[mt][0], afr[mt][1], afr[mt][2], afr[mt][3]);
            }
            #pragma unroll
            for (int np = 0; np < 4; np++) {
                int rowb = ks * 16 + (lane & 15);
                int colb = wn * 64 + np * 16 + (lane >> 4) * 8;
                uint32_t b0, b1, b2, b3;
                ldsm_x4_t(smem_u32(&Wb[rowb][colb]), b0, b1, b2, b3);
                #pragma unroll
                for (int mt = 0; mt < 2; mt++) {
                    mma16816(acc[mt][np * 2 + 0], afr[mt], b0, b1);
                    mma16816(acc[mt][np * 2 + 1], afr[mt], b2, b3);
                }
            }
        }
        if (it + 2 < 16) loadTile((it + 2) % 3, it + 2);
    }

    const int g = lane >> 2, q = lane & 3;
    #pragma unroll
    for (int mt = 0; mt < 2; mt++) {
        #pragma unroll
        for (int nt = 0; nt < 8; nt++) {
            int r = m0 + wm * 32 + mt * 16 + g;
            int c = n0 + wn * 64 + nt * 8 + q * 2;
            float b0 = __ldg(bias + c), b1 = __ldg(bias + c + 1);
            *(uint32_t*)(out + (size_t)r * N + c) =
                pack_bf16((acc[mt][nt][0] + b0) * oscale, (acc[mt][nt][1] + b1) * oscale);
            *(uint32_t*)(out + (size_t)(r + 8) * N + c) =
                pack_bf16((acc[mt][nt][2] + b0) * oscale, (acc[mt][nt][3] + b1) * oscale);
        }
    }
}

// ---------------- attention: HMMA everywhere + TC diagnostic on CTA(0,0,0) ----------------
__global__ void __launch_bounds__(256) attn_kernel(
    const float* __restrict__ x, const float* __restrict__ gamma,
    float* __restrict__ out)
{
    extern __shared__ char smem[];
    const int tid  = threadIdx.x;
    const int lane = tid & 31;
    const int warp = tid >> 5;
    const int qt = blockIdx.x, h = blockIdx.y, b = blockIdx.z;

    // ======== HMMA path (proven R3) ========
    {
        __nv_bfloat16 (*Qs)[40] = (__nv_bfloat16(*)[40])(smem);
        const __nv_bfloat16* Qg = g_Q + ((size_t)(b * Mn + qt * 128)) * 256 + h * DQK;
        const __nv_bfloat16* Kg = g_K + ((size_t)(b * Mn)) * 256 + h * DQK;
        const __nv_bfloat16* Vg = g_V + ((size_t)(b * Mn)) * 1024 + h * DV;

        auto Kst = [&](int s) { return (__nv_bfloat16(*)[40])(smem + 10240 + s * 10240); };
        auto Vst = [&](int s) { return (__nv_bfloat16(*)[136])(smem + 40960 + s * 34816); };

        auto loadKV = [&](int s, int kt) {
            __nv_bfloat16 (*Ks)[40]  = Kst(s);
            __nv_bfloat16 (*Vs)[136] = Vst(s);
            #pragma unroll
            for (int i = 0; i < 2; i++) {
                int idx = tid + i * 256;
                int r = idx >> 2, c = idx & 3;
                cp16(&Ks[r][c * 8], Kg + (size_t)(kt * 128 + r) * 256 + c * 8);
            }
            #pragma unroll
            for (int i = 0; i < 8; i++) {
                int idx = tid + i * 256;
                int r = idx >> 4, c = idx & 15;
                cp16(&Vs[r][c * 8], Vg + (size_t)(kt * 128 + r) * 1024 + c * 8);
            }
            cp_commit();
        };

        #pragma unroll
        for (int i = 0; i < 2; i++) {
            int idx = tid + i * 256;
            int r = idx >> 2, c = idx & 3;
            *(int4*)(&Qs[r][c * 8]) = *(const int4*)(Qg + (size_t)r * 256 + c * 8);
        }
        loadKV(0, 0);
        loadKV(1, 1);
        __syncthreads();

        uint32_t qfr[2][4];
        const int qrow0 = warp * 16;
        #pragma unroll
        for (int kc = 0; kc < 2; kc++) {
            int row = qrow0 + ((lane >> 3) & 1) * 8 + (lane & 7);
            int col = kc * 16 + (lane >> 4) * 8;
            ldsm_x4(smem_u32(&Qs[row][col]), qfr[kc][0], qfr[kc][1], qfr[kc][2], qfr[kc][3]);
        }

        float oacc[16][4];
        #pragma unroll
        for (int i = 0; i < 16; i++)
            #pragma unroll
            for (int j = 0; j < 4; j++) oacc[i][j] = 0.f;
        float l0 = 0.f, l1 = 0.f;

        for (int kt = 0; kt < 16; kt++) {
            if (kt < 15) cp_wait<1>(); else cp_wait<0>();
            __syncthreads();
            __nv_bfloat16 (*Ks)[40]  = Kst(kt % 3);
            __nv_bfloat16 (*Vs)[136] = Vst(kt % 3);

            float sc[16][4];
            #pragma unroll
            for (int nt = 0; nt < 16; nt++) {
                sc[nt][0] = sc[nt][1] = sc[nt][2] = sc[nt][3] = 0.f;
                int rowb = nt * 8 + (lane & 7);
                int colb = (lane >> 3) * 8;
                uint32_t k0, k1, k2, k3;
                ldsm_x4(smem_u32(&Ks[rowb][colb]), k0, k1, k2, k3);
                mma16816(sc[nt], qfr[0], k0, k1);
                mma16816(sc[nt], qfr[1], k2, k3);
            }

            float s0 = 0.f, s1 = 0.f;
            #pragma unroll
            for (int nt = 0; nt < 16; nt++) {
                #pragma unroll
                for (int j = 0; j < 4; j++) {
                    float v = sc[nt][j];
                    v = fmaxf(v, SLOPE * v);
                    v = ex2(v);
                    sc[nt][j] = v;
                    if (j < 2) s0 += v; else s1 += v;
                }
            }
            l0 += s0;
            l1 += s1;

            #pragma unroll
            for (int kc = 0; kc < 8; kc++) {
                uint32_t pa[4];
                pa[0] = pack_bf16(sc[2 * kc][0],     sc[2 * kc][1]);
                pa[1] = pack_bf16(sc[2 * kc][2],     sc[2 * kc][3]);
                pa[2] = pack_bf16(sc[2 * kc + 1][0], sc[2 * kc + 1][1]);
                pa[3] = pack_bf16(sc[2 * kc + 1][2], sc[2 * kc + 1][3]);
                #pragma unroll
                for (int dp = 0; dp < 8; dp++) {
                    int rowb = kc * 16 + (lane & 15);
                    int colb = dp * 16 + (lane >> 4) * 8;
                    uint32_t v0, v1, v2, v3;
                    ldsm_x4_t(smem_u32(&Vs[rowb][colb]), v0, v1, v2, v3);
                    mma16816(oacc[dp * 2 + 0], pa, v0, v1);
                    mma16816(oacc[dp * 2 + 1], pa, v2, v3);
                }
            }
            if (kt + 2 < 16) loadKV((kt + 2) % 3, kt + 2);
        }

        l0 += __shfl_xor_sync(0xffffffffu, l0, 1);
        l0 += __shfl_xor_sync(0xffffffffu, l0, 2);
        l1 += __shfl_xor_sync(0xffffffffu, l1, 1);
        l1 += __shfl_xor_sync(0xffffffffu, l1, 2);

        const float gm = gamma[0];
        const float il0 = gm / l0, il1 = gm / l1;
        const int g = lane >> 2, q = lane & 3;
        const size_t row0 = (size_t)b * Mn + qt * 128 + qrow0 + g;
        const size_t row1 = row0 + 8;
        #pragma unroll
        for (int d = 0; d < 16; d++) {
            int col = h * DV + d * 8 + q * 2;
            float2 x0 = *(const float2*)(x + row0 * Cn + col);
            float2 x1 = *(const float2*)(x + row1 * Cn + col);
            float2 r0, r1;
            r0.x = oacc[d][0] * il0 + x0.x;
            r0.y = oacc[d][1] * il0 + x0.y;
            r1.x = oacc[d][2] * il1 + x1.x;
            r1.y = oacc[d][3] * il1 + x1.y;
            *(float2*)(out + row0 * Cn + col) = r0;
            *(float2*)(out + row1 * Cn + col) = r1;
        }
    }

#if HAS_TC
    // ======== tcgen05 diagnostic: CTA(0,0,0) recomputes its tile (verbatim R9 core) ========
    if (qt == 0 && h == 0 && b == 0) {
        __syncthreads();   // HMMA path fully done in this CTA; smem reusable
        __shared__ uint32_t s_tptr[1];
        __shared__ __align__(8) uint64_t s_mbar[1];
        __shared__ float s_lsum[2][128];
        const int hf = warp >> 2;
        const int sp = warp & 3;
        const uint32_t spoff = (uint32_t)sp << 21;
        const __nv_bfloat16* Qg = g_Q;          // b=h=qt=0
        const __nv_bfloat16* Kg = g_K;
        const __nv_bfloat16* Vtg = g_Vt0;       // trivially-correct transpose
        const uint32_t mbar = smem_u32(s_mbar);
        const uint32_t IDESC = (1u << 4) | (1u << 7) | (1u << 10) | (16u << 17) | (8u << 24);

        auto loadK = [&](int tile) {
            char* base = smem + (tile & 1) * 16384;
            #pragma unroll
            for (int i = 0; i < 2; i++) {
                int idx = tid + i * 256; int r = idx >> 2, c = idx & 3;
                cp16(base + r * 128 + ((c ^ (r & 7)) * 16),
                     Kg + (size_t)(tile * 128 + r) * 256 + c * 8);
            }
        };
        auto loadVt = [&](int tile) {
            char* base = smem + 32768 + (tile % 3) * 32768;
            #pragma unroll
            for (int i = 0; i < 8; i++) {
                int idx = tid + i * 256;
                int n = idx >> 4, c = idx & 15;
                uint32_t off = (uint32_t)((c >> 3) * 16384 + n * 128
                                          + (((c & 7) ^ (n & 7)) * 16));
                cp16(base + off, Vtg + (size_t)n * Mn + tile * 128 + c * 8);
            }
        };

        loadK(0); loadVt(0); cp_commit();
        loadK(1); loadVt(1); cp_commit();

        if (warp == 0) TCG_ALLOC(smem_u32(s_tptr), 512);
        if (tid == 0) MBAR_INIT(mbar, 1);
        __syncthreads();
        const uint32_t tb = s_tptr[0];

        if (warp < 4) {
            const uint4* qrow = (const uint4*)(Qg + (size_t)(warp * 32 + lane) * 256);
            uint32_t qr[16];
            #pragma unroll
            for (int i = 0; i < 4; i++) {
                uint4 v = qrow[i];
                qr[4 * i] = v.x; qr[4 * i + 1] = v.y; qr[4 * i + 2] = v.z; qr[4 * i + 3] = v.w;
            }
            TCG_ST_X16(tb + ((uint32_t)warp << 21), qr);
            TCG_WAIT_ST();
        }
        TCG_FENCE_B();
        __syncthreads();

        uint32_t ph = 0;
        float lsum = 0.f;

        for (int kt = 0; kt < 16; kt++) {
            if (kt < 15) cp_wait<1>(); else cp_wait<0>();
            FENCE_ASYNC();
            __syncthreads();

            if (warp == 0 && elect_one_pred()) {
                TCG_FENCE_A();
                uint64_t kd = desc_k(smem_u32(smem + (kt & 1) * 16384));
                mma_f16_ts(tb + 64, tb + 0, kd, IDESC, false);
                mma_f16_ts(tb + 64, tb + 8, kd + 2, IDESC, true);
                TCG_COMMIT(mbar);
            }
            MBAR_WAIT(mbar, ph); ph ^= 1;

            if (kt + 2 < 16) { loadK(kt + 2); loadVt(kt + 2); cp_commit(); }

            TCG_FENCE_A();
            #pragma unroll
            for (int ch = 0; ch < 2; ch++) {
                uint32_t r[32];
                TCG_LD_X32(r, tb + 64 + hf * 64 + ch * 32);
                TCG_WAIT_LD();
                uint32_t p[16];
                #pragma unroll
                for (int jj = 0; jj < 16; jj++) {
                    float v0 = __uint_as_float(r[2 * jj]);
                    float v1 = __uint_as_float(r[2 * jj + 1]);
                    v0 = fmaxf(v0, SLOPE * v0); v1 = fmaxf(v1, SLOPE * v1);
                    v0 = ex2(v0); v1 = ex2(v1);
                    lsum += v0 + v1;
                    p[jj] = pack_bf16(v0, v1);
                }
                TCG_ST_X16(tb + 192 + hf * 32 + ch * 16 + spoff, p);
            }
            TCG_WAIT_ST();
            TCG_FENCE_B();
            __syncthreads();

            if (warp == 0 && elect_one_pred()) {
                TCG_FENCE_A();
                uint32_t vtb = smem_u32(smem + 32768 + (kt % 3) * 32768);
                uint64_t vd0 = desc_k(vtb);
                uint64_t vd1 = desc_k(vtb + 16384);
                #pragma unroll
                for (int s = 0; s < 8; s++) {
                    uint64_t vd = (s < 4 ? vd0 : vd1) + (uint64_t)((s & 3) * 2);
                    mma_f16_ts(tb + 256, tb + 192 + s * 8, vd, IDESC, (kt > 0) || (s > 0));
                }
                TCG_COMMIT(mbar);
            }
            MBAR_WAIT(mbar, ph); ph ^= 1;
        }
        TCG_FENCE_A();

        s_lsum[hf][sp * 32 + lane] = lsum;
        __syncthreads();

        {
            const int row_t = sp * 32 + lane;
            const float sc = __ldg(gamma) / (s_lsum[0][row_t] + s_lsum[1][row_t]);
            const size_t row = (size_t)row_t;   // b=qt=0
            const float4* xr = (const float4*)(x + row * Cn + hf * 64);
            float4* orow = (float4*)(out + row * Cn + hf * 64);
            #pragma unroll
            for (int ch = 0; ch < 2; ch++) {
                uint32_t r[32];
                TCG_LD_X32(r, tb + 256 + hf * 64 + ch * 32);
                TCG_WAIT_LD();
                #pragma unroll
                for (int jj = 0; jj < 8; jj++) {
                    float4 xv = xr[ch * 8 + jj];
                    float4 ov;
                    ov.x = __uint_as_float(r[4 * jj + 0]) * sc + xv.x;
                    ov.y = __uint_as_float(r[4 * jj + 1]) * sc + xv.y;
                    ov.z = __uint_as_float(r[4 * jj + 2]) * sc + xv.z;
                    ov.w = __uint_as_float(r[4 * jj + 3]) * sc + xv.w;
                    orow[ch * 8 + jj] = ov;
                }
            }
        }
        __syncthreads();
        if (tid == 0)
            asm volatile("mbarrier.inval.shared.b64 [%0];" :: "r"(mbar) : "memory");
        __syncthreads();
        if (warp == 0) TCG_DEALLOC(tb, 512);
    }
#endif
}

// ---------------- launch ----------------
extern "C" void kernel_launch(void* const* d_in, const int* in_sizes, int n_in,
                              void* d_out, int out_size)
{
    const float* x     = (const float*)d_in[0];
    const float* y     = (const float*)d_in[1];
    const float* Wq    = (const float*)d_in[2];
    const float* bq    = (const float*)d_in[3];
    const float* Wk    = (const float*)d_in[4];
    const float* bk    = (const float*)d_in[5];
    const float* Wv    = (const float*)d_in[6];
    const float* bv    = (const float*)d_in[7];
    const float* gamma = (const float*)d_in[8];
    float* out = (float*)d_out;

    cvt_all<<<4480, 256>>>(x, y, Wq, Wk, Wv);

    const int gemm_smem = 3 * 35840;
    cudaFuncSetAttribute(gemm_fused, cudaFuncAttributeMaxDynamicSharedMemorySize, gemm_smem);
    gemm_fused<<<768, 256, gemm_smem>>>(bq, bk, bv);

    mk_vt0<<<16, 256>>>();

    const int attn_smem = 147456;  // HMMA 145408; TC diag 131072
    cudaFuncSetAttribute(attn_kernel, cudaFuncAttributeMaxDynamicSharedMemorySize, attn_smem);
    attn_kernel<<<dim3(16, 8, 4), 256, attn_smem>>>(x, gamma, out);
}

// round 12
// speedup vs baseline: 1.1707x; 1.1707x over previous
#include <cuda_runtime.h>
#include <cuda_bf16.h>
#include <math.h>
#include <stdint.h>

#define Bn   4
#define Mn   2048
#define Cn   1024
#define Hn   8
#define DQK  32
#define DV   128
#define ROWS (Bn*Mn)
#define SLOPE 0.2f
#define QSCALE 0.25503695218998236f  // (1/sqrt(32))*log2(e)

__device__ __nv_bfloat16 g_Xb[ROWS * Cn];
__device__ __nv_bfloat16 g_Yb[ROWS * Cn];
__device__ __nv_bfloat16 g_Wqb[Cn * 256];
__device__ __nv_bfloat16 g_Wkb[Cn * 256];
__device__ __nv_bfloat16 g_Wvb[Cn * Cn];
__device__ __nv_bfloat16 g_Q[ROWS * 256];
__device__ __nv_bfloat16 g_K[ROWS * 256];
__device__ __nv_bfloat16 g_V[ROWS * 1024];

// ---------------- helpers ----------------
__device__ __forceinline__ uint32_t smem_u32(const void* p) {
    return (uint32_t)__cvta_generic_to_shared(p);
}
__device__ __forceinline__ uint32_t pack_bf16(float lo, float hi) {
    uint32_t r;
    asm("cvt.rn.bf16x2.f32 %0, %1, %2;" : "=r"(r) : "f"(hi), "f"(lo));
    return r;
}
__device__ __forceinline__ float ex2(float x) {
    float r; asm("ex2.approx.f32 %0, %1;" : "=f"(r) : "f"(x)); return r;
}
__device__ __forceinline__ void ldsm_x4(uint32_t a, uint32_t& r0, uint32_t& r1,
                                        uint32_t& r2, uint32_t& r3) {
    asm volatile("ldmatrix.sync.aligned.m8n8.x4.shared.b16 {%0,%1,%2,%3}, [%4];"
                 : "=r"(r0), "=r"(r1), "=r"(r2), "=r"(r3) : "r"(a));
}
__device__ __forceinline__ void ldsm_x4_t(uint32_t a, uint32_t& r0, uint32_t& r1,
                                          uint32_t& r2, uint32_t& r3) {
    asm volatile("ldmatrix.sync.aligned.m8n8.x4.trans.shared.b16 {%0,%1,%2,%3}, [%4];"
                 : "=r"(r0), "=r"(r1), "=r"(r2), "=r"(r3) : "r"(a));
}
__device__ __forceinline__ void mma16816(float* c, const uint32_t* a, uint32_t b0, uint32_t b1) {
    asm volatile(
        "mma.sync.aligned.m16n8k16.row.col.f32.bf16.bf16.f32 "
        "{%0,%1,%2,%3}, {%4,%5,%6,%7}, {%8,%9}, {%0,%1,%2,%3};"
        : "+f"(c[0]), "+f"(c[1]), "+f"(c[2]), "+f"(c[3])
        : "r"(a[0]), "r"(a[1]), "r"(a[2]), "r"(a[3]), "r"(b0), "r"(b1));
}
__device__ __forceinline__ void cp16(void* dst, const void* src) {
    asm volatile("cp.async.cg.shared.global [%0], [%1], 16;"
                 :: "r"(smem_u32(dst)), "l"(src) : "memory");
}
__device__ __forceinline__ void cp_commit() {
    asm volatile("cp.async.commit_group;" ::: "memory");
}
template <int N>
__device__ __forceinline__ void cp_wait() {
    asm volatile("cp.async.wait_group %0;" :: "n"(N) : "memory");
}

// ---------------- fp32 -> bf16 convert (4 float4 per thread) ----------------
__global__ void __launch_bounds__(256) cvt_all(
    const float* __restrict__ x, const float* __restrict__ y,
    const float* __restrict__ wq, const float* __restrict__ wk,
    const float* __restrict__ wv)
{
    int bid = blockIdx.x;
    const float* src;
    __nv_bfloat16* dst;
    int base;
    if (bid < 2048)      { src = x;  dst = g_Xb;  base = bid; }
    else if (bid < 4096) { src = y;  dst = g_Yb;  base = bid - 2048; }
    else if (bid < 4160) { src = wq; dst = g_Wqb; base = bid - 4096; }
    else if (bid < 4224) { src = wk; dst = g_Wkb; base = bid - 4160; }
    else                 { src = wv; dst = g_Wvb; base = bid - 4224; }
    #pragma unroll
    for (int i = 0; i < 4; i++) {
        size_t off = (size_t)base * 4096 + i * 1024 + threadIdx.x * 4;
        float4 f = *(const float4*)(src + off);
        uint2 u;
        u.x = pack_bf16(f.x, f.y);
        u.y = pack_bf16(f.z, f.w);
        *(uint2*)(dst + off) = u;
    }
}

// ---------------- fused projection GEMM (proven R3 version) ----------------
__global__ void __launch_bounds__(256) gemm_fused(
    const float* __restrict__ bq, const float* __restrict__ bk,
    const float* __restrict__ bv)
{
    extern __shared__ char smem[];
    auto Ast = [&](int s) { return (__nv_bfloat16(*)[72])(smem + s * 35840); };
    auto Wst = [&](int s) { return (__nv_bfloat16(*)[136])(smem + s * 35840 + 18432); };

    const int tid  = threadIdx.x;
    const int lane = tid & 31;
    const int warp = tid >> 5;
    const int wm   = warp >> 1;
    const int wn   = warp & 1;

    int bid = blockIdx.x;
    const __nv_bfloat16 *A, *W;
    const float* bias;
    __nv_bfloat16* out;
    int N, bx, by;
    float oscale;
    if (bid < 128)      { A = g_Xb; W = g_Wqb; bias = bq; out = g_Q; N = 256;
                          bx = bid & 1;  by = bid >> 1; oscale = QSCALE; }
    else if (bid < 256) { bid -= 128; A = g_Yb; W = g_Wkb; bias = bk; out = g_K; N = 256;
                          bx = bid & 1;  by = bid >> 1; oscale = 1.f; }
    else                { bid -= 256; A = g_Yb; W = g_Wvb; bias = bv; out = g_V; N = 1024;
                          bx = bid & 7;  by = bid >> 3; oscale = 1.f; }
    const int m0 = by * 128;
    const int n0 = bx * 128;

    auto loadTile = [&](int s, int it) {
        __nv_bfloat16 (*Ad)[72]  = Ast(s);
        __nv_bfloat16 (*Wd)[136] = Wst(s);
        #pragma unroll
        for (int i = 0; i < 4; i++) {
            int idx = tid + i * 256;
            int r = idx >> 3, c = idx & 7;
            cp16(&Ad[r][c * 8], A + (size_t)(m0 + r) * 1024 + it * 64 + c * 8);
        }
        #pragma unroll
        for (int i = 0; i < 4; i++) {
            int idx = tid + i * 256;
            int r = idx >> 4, c = idx & 15;
            cp16(&Wd[r][c * 8], W + (size_t)(it * 64 + r) * N + n0 + c * 8);
        }
        cp_commit();
    };

    float acc[2][8][4] = {};
    loadTile(0, 0);
    loadTile(1, 1);

    for (int it = 0; it < 16; it++) {
        if (it < 15) cp_wait<1>(); else cp_wait<0>();
        __syncthreads();
        __nv_bfloat16 (*Ab)[72]  = Ast(it % 3);
        __nv_bfloat16 (*Wb)[136] = Wst(it % 3);
        #pragma unroll
        for (int ks = 0; ks < 4; ks++) {
            uint32_t afr[2][4];
            #pragma unroll
            for (int mt = 0; mt < 2; mt++) {
                int row = wm * 32 + mt * 16 + ((lane >> 3) & 1) * 8 + (lane & 7);
                int col = ks * 16 + (lane >> 4) * 8;
                ldsm_x4(smem_u32(&Ab[row][col]), afr[mt][0], afr[mt][1], afr[mt][2], afr[mt][3]);
            }
            #pragma unroll
            for (int np = 0; np < 4; np++) {
                int rowb = ks * 16 + (lane & 15);
                int colb = wn * 64 + np * 16 + (lane >> 4) * 8;
                uint32_t b0, b1, b2, b3;
                ldsm_x4_t(smem_u32(&Wb[rowb][colb]), b0, b1, b2, b3);
                #pragma unroll
                for (int mt = 0; mt < 2; mt++) {
                    mma16816(acc[mt][np * 2 + 0], afr[mt], b0, b1);
                    mma16816(acc[mt][np * 2 + 1], afr[mt], b2, b3);
                }
            }
        }
        if (it + 2 < 16) loadTile((it + 2) % 3, it + 2);
    }

    const int g = lane >> 2, q = lane & 3;
    #pragma unroll
    for (int mt = 0; mt < 2; mt++) {
        #pragma unroll
        for (int nt = 0; nt < 8; nt++) {
            int r = m0 + wm * 32 + mt * 16 + g;
            int c = n0 + wn * 64 + nt * 8 + q * 2;
            float b0 = __ldg(bias + c), b1 = __ldg(bias + c + 1);
            *(uint32_t*)(out + (size_t)r * N + c) =
                pack_bf16((acc[mt][nt][0] + b0) * oscale, (acc[mt][nt][1] + b1) * oscale);
            *(uint32_t*)(out + (size_t)(r + 8) * N + c) =
                pack_bf16((acc[mt][nt][2] + b0) * oscale, (acc[mt][nt][3] + b1) * oscale);
        }
    }
}

// ---------------- flash attention, dv-split for 2 CTAs/SM ----------------
// grid (qt=16, h*2+dvh=16, b=4). CTA: 128 q rows x 64 dv (half). 8 warps x 16 rows.
// QK + softmax duplicated across the dv-half pair; PV and V traffic halved per CTA.
// smem: Q [128][40] @0 | K 3x[128][40] @10240 | Vh 3x[128][72] @40960  (96,256 B)
__global__ void __launch_bounds__(256, 2) attn_kernel(
    const float* __restrict__ x, const float* __restrict__ gamma,
    float* __restrict__ out)
{
    extern __shared__ char smem[];
    __nv_bfloat16 (*Qs)[40] = (__nv_bfloat16(*)[40])(smem);
    const int tid  = threadIdx.x;
    const int lane = tid & 31;
    const int warp = tid >> 5;
    const int qt = blockIdx.x, b = blockIdx.z;
    const int h = blockIdx.y >> 1, dvh = blockIdx.y & 1;

    const __nv_bfloat16* Qg = g_Q + ((size_t)(b * Mn + qt * 128)) * 256 + h * DQK;
    const __nv_bfloat16* Kg = g_K + ((size_t)(b * Mn)) * 256 + h * DQK;
    const __nv_bfloat16* Vg = g_V + ((size_t)(b * Mn)) * 1024 + h * DV + dvh * 64;

    auto Kst = [&](int s) { return (__nv_bfloat16(*)[40])(smem + 10240 + s * 10240); };
    auto Vst = [&](int s) { return (__nv_bfloat16(*)[72])(smem + 40960 + s * 18432); };

    auto loadKV = [&](int s, int kt) {
        __nv_bfloat16 (*Ks)[40] = Kst(s);
        __nv_bfloat16 (*Vs)[72] = Vst(s);
        // K tile: 128 rows x 32 bf16 = 512 chunks of 16B
        #pragma unroll
        for (int i = 0; i < 2; i++) {
            int idx = tid + i * 256;
            int r = idx >> 2, c = idx & 3;
            cp16(&Ks[r][c * 8], Kg + (size_t)(kt * 128 + r) * 256 + c * 8);
        }
        // V half tile: 128 rows x 64 bf16 = 1024 chunks of 16B
        #pragma unroll
        for (int i = 0; i < 4; i++) {
            int idx = tid + i * 256;
            int r = idx >> 3, c = idx & 7;
            cp16(&Vs[r][c * 8], Vg + (size_t)(kt * 128 + r) * 1024 + c * 8);
        }
        cp_commit();
    };

    // Q tile [128][32]
    #pragma unroll
    for (int i = 0; i < 2; i++) {
        int idx = tid + i * 256;
        int r = idx >> 2, c = idx & 3;
        *(int4*)(&Qs[r][c * 8]) = *(const int4*)(Qg + (size_t)r * 256 + c * 8);
    }
    loadKV(0, 0);
    loadKV(1, 1);
    __syncthreads();

    // Q fragments (fixed)
    uint32_t qfr[2][4];
    const int qrow0 = warp * 16;
    #pragma unroll
    for (int kc = 0; kc < 2; kc++) {
        int row = qrow0 + ((lane >> 3) & 1) * 8 + (lane & 7);
        int col = kc * 16 + (lane >> 4) * 8;
        ldsm_x4(smem_u32(&Qs[row][col]), qfr[kc][0], qfr[kc][1], qfr[kc][2], qfr[kc][3]);
    }

    float oacc[8][4];
    #pragma unroll
    for (int i = 0; i < 8; i++)
        #pragma unroll
        for (int j = 0; j < 4; j++) oacc[i][j] = 0.f;
    float l0 = 0.f, l1 = 0.f;

    for (int kt = 0; kt < 16; kt++) {
        if (kt < 15) cp_wait<1>(); else cp_wait<0>();
        __syncthreads();
        __nv_bfloat16 (*Ks)[40] = Kst(kt % 3);
        __nv_bfloat16 (*Vs)[72] = Vst(kt % 3);

        // scores [16 x 128] per warp (log2 domain via QSCALE)
        float sc[16][4];
        #pragma unroll
        for (int nt = 0; nt < 16; nt++) {
            sc[nt][0] = sc[nt][1] = sc[nt][2] = sc[nt][3] = 0.f;
            int rowb = nt * 8 + (lane & 7);
            int colb = (lane >> 3) * 8;
            uint32_t k0, k1, k2, k3;
            ldsm_x4(smem_u32(&Ks[rowb][colb]), k0, k1, k2, k3);
            mma16816(sc[nt], qfr[0], k0, k1);
            mma16816(sc[nt], qfr[1], k2, k3);
        }

        // leaky + exp2 + row-sum (no running max; scores bounded)
        float s0 = 0.f, s1 = 0.f;
        #pragma unroll
        for (int nt = 0; nt < 16; nt++) {
            #pragma unroll
            for (int j = 0; j < 4; j++) {
                float v = sc[nt][j];
                v = fmaxf(v, SLOPE * v);
                v = ex2(v);
                sc[nt][j] = v;
                if (j < 2) s0 += v; else s1 += v;
            }
        }
        l0 += s0;
        l1 += s1;

        // PV on this CTA's 64-dv half
        #pragma unroll
        for (int kc = 0; kc < 8; kc++) {
            uint32_t pa[4];
            pa[0] = pack_bf16(sc[2 * kc][0],     sc[2 * kc][1]);
            pa[1] = pack_bf16(sc[2 * kc][2],     sc[2 * kc][3]);
            pa[2] = pack_bf16(sc[2 * kc + 1][0], sc[2 * kc + 1][1]);
            pa[3] = pack_bf16(sc[2 * kc + 1][2], sc[2 * kc + 1][3]);
            #pragma unroll
            for (int dp = 0; dp < 4; dp++) {
                int rowb = kc * 16 + (lane & 15);
                int colb = dp * 16 + (lane >> 4) * 8;
                uint32_t v0, v1, v2, v3;
                ldsm_x4_t(smem_u32(&Vs[rowb][colb]), v0, v1, v2, v3);
                mma16816(oacc[dp * 2 + 0], pa, v0, v1);
                mma16816(oacc[dp * 2 + 1], pa, v2, v3);
            }
        }
        if (kt + 2 < 16) loadKV((kt + 2) % 3, kt + 2);
    }

    // row-sum reduce across quad (key columns split over 4 lanes)
    l0 += __shfl_xor_sync(0xffffffffu, l0, 1);
    l0 += __shfl_xor_sync(0xffffffffu, l0, 2);
    l1 += __shfl_xor_sync(0xffffffffu, l1, 1);
    l1 += __shfl_xor_sync(0xffffffffu, l1, 2);

    // epilogue: out = gamma * O / l + x  (this CTA's dv-half columns)
    const float gm = gamma[0];
    const float il0 = gm / l0, il1 = gm / l1;
    const int g = lane >> 2, q = lane & 3;
    const size_t row0 = (size_t)b * Mn + qt * 128 + qrow0 + g;
    const size_t row1 = row0 + 8;
    #pragma unroll
    for (int d = 0; d < 8; d++) {
        int col = h * DV + dvh * 64 + d * 8 + q * 2;
        float2 x0 = *(const float2*)(x + row0 * Cn + col);
        float2 x1 = *(const float2*)(x + row1 * Cn + col);
        float2 r0, r1;
        r0.x = oacc[d][0] * il0 + x0.x;
        r0.y = oacc[d][1] * il0 + x0.y;
        r1.x = oacc[d][2] * il1 + x1.x;
        r1.y = oacc[d][3] * il1 + x1.y;
        *(float2*)(out + row0 * Cn + col) = r0;
        *(float2*)(out + row1 * Cn + col) = r1;
    }
}

// ---------------- launch ----------------
extern "C" void kernel_launch(void* const* d_in, const int* in_sizes, int n_in,
                              void* d_out, int out_size)
{
    const float* x     = (const float*)d_in[0];
    const float* y     = (const float*)d_in[1];
    const float* Wq    = (const float*)d_in[2];
    const float* bq    = (const float*)d_in[3];
    const float* Wk    = (const float*)d_in[4];
    const float* bk    = (const float*)d_in[5];
    const float* Wv    = (const float*)d_in[6];
    const float* bv    = (const float*)d_in[7];
    const float* gamma = (const float*)d_in[8];
    float* out = (float*)d_out;

    cvt_all<<<4480, 256>>>(x, y, Wq, Wk, Wv);

    const int gemm_smem = 3 * 35840;
    cudaFuncSetAttribute(gemm_fused, cudaFuncAttributeMaxDynamicSharedMemorySize, gemm_smem);
    gemm_fused<<<768, 256, gemm_smem>>>(bq, bk, bv);

    const int attn_smem = 40960 + 3 * 18432;  // 96,256 -> 2 CTAs/SM
    cudaFuncSetAttribute(attn_kernel, cudaFuncAttributeMaxDynamicSharedMemorySize, attn_smem);
    attn_kernel<<<dim3(16, 16, 4), 256, attn_smem>>>(x, gamma, out);
}

// round 13
// speedup vs baseline: 1.1813x; 1.0090x over previous
#include <cuda_runtime.h>
#include <cuda_bf16.h>
#include <math.h>
#include <stdint.h>

#define Bn   4
#define Mn   2048
#define Cn   1024
#define Hn   8
#define DQK  32
#define DV   128
#define ROWS (Bn*Mn)
#define SLOPE 0.2f
#define QSCALE 0.25503695218998236f  // (1/sqrt(32))*log2(e)

__device__ __nv_bfloat16 g_Xb[ROWS * Cn];
__device__ __nv_bfloat16 g_Yb[ROWS * Cn];
__device__ __nv_bfloat16 g_Wqb[Cn * 256];
__device__ __nv_bfloat16 g_Wkb[Cn * 256];
__device__ __nv_bfloat16 g_Wvb[Cn * Cn];
__device__ __nv_bfloat16 g_Q[ROWS * 256];
__device__ __nv_bfloat16 g_K[ROWS * 256];
__device__ __nv_bfloat16 g_V[ROWS * 1024];

// ---------------- helpers ----------------
__device__ __forceinline__ uint32_t smem_u32(const void* p) {
    return (uint32_t)__cvta_generic_to_shared(p);
}
__device__ __forceinline__ uint32_t pack_bf16(float lo, float hi) {
    uint32_t r;
    asm("cvt.rn.bf16x2.f32 %0, %1, %2;" : "=r"(r) : "f"(hi), "f"(lo));
    return r;
}
__device__ __forceinline__ float ex2(float x) {
    float r; asm("ex2.approx.f32 %0, %1;" : "=f"(r) : "f"(x)); return r;
}
__device__ __forceinline__ void ldsm_x4(uint32_t a, uint32_t& r0, uint32_t& r1,
                                        uint32_t& r2, uint32_t& r3) {
    asm volatile("ldmatrix.sync.aligned.m8n8.x4.shared.b16 {%0,%1,%2,%3}, [%4];"
                 : "=r"(r0), "=r"(r1), "=r"(r2), "=r"(r3) : "r"(a));
}
__device__ __forceinline__ void ldsm_x4_t(uint32_t a, uint32_t& r0, uint32_t& r1,
                                          uint32_t& r2, uint32_t& r3) {
    asm volatile("ldmatrix.sync.aligned.m8n8.x4.trans.shared.b16 {%0,%1,%2,%3}, [%4];"
                 : "=r"(r0), "=r"(r1), "=r"(r2), "=r"(r3) : "r"(a));
}
__device__ __forceinline__ void mma16816(float* c, const uint32_t* a, uint32_t b0, uint32_t b1) {
    asm volatile(
        "mma.sync.aligned.m16n8k16.row.col.f32.bf16.bf16.f32 "
        "{%0,%1,%2,%3}, {%4,%5,%6,%7}, {%8,%9}, {%0,%1,%2,%3};"
        : "+f"(c[0]), "+f"(c[1]), "+f"(c[2]), "+f"(c[3])
        : "r"(a[0]), "r"(a[1]), "r"(a[2]), "r"(a[3]), "r"(b0), "r"(b1));
}
__device__ __forceinline__ void cp16(void* dst, const void* src) {
    asm volatile("cp.async.cg.shared.global [%0], [%1], 16;"
                 :: "r"(smem_u32(dst)), "l"(src) : "memory");
}
__device__ __forceinline__ void cp_commit() {
    asm volatile("cp.async.commit_group;" ::: "memory");
}
template <int N>
__device__ __forceinline__ void cp_wait() {
    asm volatile("cp.async.wait_group %0;" :: "n"(N) : "memory");
}

// ---------------- fp32 -> bf16 convert (4 float4 per thread) ----------------
__global__ void __launch_bounds__(256) cvt_all(
    const float* __restrict__ x, const float* __restrict__ y,
    const float* __restrict__ wq, const float* __restrict__ wk,
    const float* __restrict__ wv)
{
    int bid = blockIdx.x;
    const float* src;
    __nv_bfloat16* dst;
    int base;
    if (bid < 2048)      { src = x;  dst = g_Xb;  base = bid; }
    else if (bid < 4096) { src = y;  dst = g_Yb;  base = bid - 2048; }
    else if (bid < 4160) { src = wq; dst = g_Wqb; base = bid - 4096; }
    else if (bid < 4224) { src = wk; dst = g_Wkb; base = bid - 4160; }
    else                 { src = wv; dst = g_Wvb; base = bid - 4224; }
    #pragma unroll
    for (int i = 0; i < 4; i++) {
        size_t off = (size_t)base * 4096 + i * 1024 + threadIdx.x * 4;
        float4 f = *(const float4*)(src + off);
        uint2 u;
        u.x = pack_bf16(f.x, f.y);
        u.y = pack_bf16(f.z, f.w);
        *(uint2*)(dst + off) = u;
    }
}

// ---------------- fused projection GEMM: 2-stage, 2 CTAs/SM ----------------
__global__ void __launch_bounds__(256, 2) gemm_fused(
    const float* __restrict__ bq, const float* __restrict__ bk,
    const float* __restrict__ bv)
{
    extern __shared__ char smem[];
    auto Ast = [&](int s) { return (__nv_bfloat16(*)[72])(smem + s * 35840); };
    auto Wst = [&](int s) { return (__nv_bfloat16(*)[136])(smem + s * 35840 + 18432); };

    const int tid  = threadIdx.x;
    const int lane = tid & 31;
    const int warp = tid >> 5;
    const int wm   = warp >> 1;
    const int wn   = warp & 1;

    int bid = blockIdx.x;
    const __nv_bfloat16 *A, *W;
    const float* bias;
    __nv_bfloat16* out;
    int N, bx, by;
    float oscale;
    if (bid < 128)      { A = g_Xb; W = g_Wqb; bias = bq; out = g_Q; N = 256;
                          bx = bid & 1;  by = bid >> 1; oscale = QSCALE; }
    else if (bid < 256) { bid -= 128; A = g_Yb; W = g_Wkb; bias = bk; out = g_K; N = 256;
                          bx = bid & 1;  by = bid >> 1; oscale = 1.f; }
    else                { bid -= 256; A = g_Yb; W = g_Wvb; bias = bv; out = g_V; N = 1024;
                          bx = bid & 7;  by = bid >> 3; oscale = 1.f; }
    const int m0 = by * 128;
    const int n0 = bx * 128;

    auto loadTile = [&](int s, int it) {
        __nv_bfloat16 (*Ad)[72]  = Ast(s);
        __nv_bfloat16 (*Wd)[136] = Wst(s);
        #pragma unroll
        for (int i = 0; i < 4; i++) {
            int idx = tid + i * 256;
            int r = idx >> 3, c = idx & 7;
            cp16(&Ad[r][c * 8], A + (size_t)(m0 + r) * 1024 + it * 64 + c * 8);
        }
        #pragma unroll
        for (int i = 0; i < 4; i++) {
            int idx = tid + i * 256;
            int r = idx >> 4, c = idx & 15;
            cp16(&Wd[r][c * 8], W + (size_t)(it * 64 + r) * N + n0 + c * 8);
        }
        cp_commit();
    };

    float acc[2][8][4] = {};
    loadTile(0, 0);

    for (int it = 0; it < 16; it++) {
        if (it < 15) {
            loadTile((it + 1) & 1, it + 1);
            cp_wait<1>();
        } else {
            cp_wait<0>();
        }
        __syncthreads();

        __nv_bfloat16 (*Ab)[72]  = Ast(it & 1);
        __nv_bfloat16 (*Wb)[136] = Wst(it & 1);
        #pragma unroll
        for (int ks = 0; ks < 4; ks++) {
            uint32_t afr[2][4];
            #pragma unroll
            for (int mt = 0; mt < 2; mt++) {
                int row = wm * 32 + mt * 16 + ((lane >> 3) & 1) * 8 + (lane & 7);
                int col = ks * 16 + (lane >> 4) * 8;
                ldsm_x4(smem_u32(&Ab[row][col]), afr[mt][0], afr[mt][1], afr[mt][2], afr[mt][3]);
            }
            #pragma unroll
            for (int np = 0; np < 4; np++) {
                int rowb = ks * 16 + (lane & 15);
                int colb = wn * 64 + np * 16 + (lane >> 4) * 8;
                uint32_t b0, b1, b2, b3;
                ldsm_x4_t(smem_u32(&Wb[rowb][colb]), b0, b1, b2, b3);
                #pragma unroll
                for (int mt = 0; mt < 2; mt++) {
                    mma16816(acc[mt][np * 2 + 0], afr[mt], b0, b1);
                    mma16816(acc[mt][np * 2 + 1], afr[mt], b2, b3);
                }
            }
        }
        __syncthreads();
    }

    const int g = lane >> 2, q = lane & 3;
    #pragma unroll
    for (int mt = 0; mt < 2; mt++) {
        #pragma unroll
        for (int nt = 0; nt < 8; nt++) {
            int r = m0 + wm * 32 + mt * 16 + g;
            int c = n0 + wn * 64 + nt * 8 + q * 2;
            float b0 = __ldg(bias + c), b1 = __ldg(bias + c + 1);
            *(uint32_t*)(out + (size_t)r * N + c) =
                pack_bf16((acc[mt][nt][0] + b0) * oscale, (acc[mt][nt][1] + b1) * oscale);
            *(uint32_t*)(out + (size_t)(r + 8) * N + c) =
                pack_bf16((acc[mt][nt][2] + b0) * oscale, (acc[mt][nt][3] + b1) * oscale);
        }
    }
}

// ---------------- flash attention, dv-split for 2 CTAs/SM (R12, passing) ----------------
__global__ void __launch_bounds__(256, 2) attn_kernel(
    const float* __restrict__ x, const float* __restrict__ gamma,
    float* __restrict__ out)
{
    extern __shared__ char smem[];
    __nv_bfloat16 (*Qs)[40] = (__nv_bfloat16(*)[40])(smem);
    const int tid  = threadIdx.x;
    const int lane = tid & 31;
    const int warp = tid >> 5;
    const int qt = blockIdx.x, b = blockIdx.z;
    const int h = blockIdx.y >> 1, dvh = blockIdx.y & 1;

    const __nv_bfloat16* Qg = g_Q + ((size_t)(b * Mn + qt * 128)) * 256 + h * DQK;
    const __nv_bfloat16* Kg = g_K + ((size_t)(b * Mn)) * 256 + h * DQK;
    const __nv_bfloat16* Vg = g_V + ((size_t)(b * Mn)) * 1024 + h * DV + dvh * 64;

    auto Kst = [&](int s) { return (__nv_bfloat16(*)[40])(smem + 10240 + s * 10240); };
    auto Vst = [&](int s) { return (__nv_bfloat16(*)[72])(smem + 40960 + s * 18432); };

    auto loadKV = [&](int s, int kt) {
        __nv_bfloat16 (*Ks)[40] = Kst(s);
        __nv_bfloat16 (*Vs)[72] = Vst(s);
        #pragma unroll
        for (int i = 0; i < 2; i++) {
            int idx = tid + i * 256;
            int r = idx >> 2, c = idx & 3;
            cp16(&Ks[r][c * 8], Kg + (size_t)(kt * 128 + r) * 256 + c * 8);
        }
        #pragma unroll
        for (int i = 0; i < 4; i++) {
            int idx = tid + i * 256;
            int r = idx >> 3, c = idx & 7;
            cp16(&Vs[r][c * 8], Vg + (size_t)(kt * 128 + r) * 1024 + c * 8);
        }
        cp_commit();
    };

    // Q tile [128][32]
    #pragma unroll
    for (int i = 0; i < 2; i++) {
        int idx = tid + i * 256;
        int r = idx >> 2, c = idx & 3;
        *(int4*)(&Qs[r][c * 8]) = *(const int4*)(Qg + (size_t)r * 256 + c * 8);
    }
    loadKV(0, 0);
    loadKV(1, 1);
    __syncthreads();

    uint32_t qfr[2][4];
    const int qrow0 = warp * 16;
    #pragma unroll
    for (int kc = 0; kc < 2; kc++) {
        int row = qrow0 + ((lane >> 3) & 1) * 8 + (lane & 7);
        int col = kc * 16 + (lane >> 4) * 8;
        ldsm_x4(smem_u32(&Qs[row][col]), qfr[kc][0], qfr[kc][1], qfr[kc][2], qfr[kc][3]);
    }

    float oacc[8][4];
    #pragma unroll
    for (int i = 0; i < 8; i++)
        #pragma unroll
        for (int j = 0; j < 4; j++) oacc[i][j] = 0.f;
    float l0 = 0.f, l1 = 0.f;

    for (int kt = 0; kt < 16; kt++) {
        if (kt < 15) cp_wait<1>(); else cp_wait<0>();
        __syncthreads();
        __nv_bfloat16 (*Ks)[40] = Kst(kt % 3);
        __nv_bfloat16 (*Vs)[72] = Vst(kt % 3);

        float sc[16][4];
        #pragma unroll
        for (int nt = 0; nt < 16; nt++) {
            sc[nt][0] = sc[nt][1] = sc[nt][2] = sc[nt][3] = 0.f;
            int rowb = nt * 8 + (lane & 7);
            int colb = (lane >> 3) * 8;
            uint32_t k0, k1, k2, k3;
            ldsm_x4(smem_u32(&Ks[rowb][colb]), k0, k1, k2, k3);
            mma16816(sc[nt], qfr[0], k0, k1);
            mma16816(sc[nt], qfr[1], k2, k3);
        }

        float s0 = 0.f, s1 = 0.f;
        #pragma unroll
        for (int nt = 0; nt < 16; nt++) {
            #pragma unroll
            for (int j = 0; j < 4; j++) {
                float v = sc[nt][j];
                v = fmaxf(v, SLOPE * v);
                v = ex2(v);
                sc[nt][j] = v;
                if (j < 2) s0 += v; else s1 += v;
            }
        }
        l0 += s0;
        l1 += s1;

        #pragma unroll
        for (int kc = 0; kc < 8; kc++) {
            uint32_t pa[4];
            pa[0] = pack_bf16(sc[2 * kc][0],     sc[2 * kc][1]);
            pa[1] = pack_bf16(sc[2 * kc][2],     sc[2 * kc][3]);
            pa[2] = pack_bf16(sc[2 * kc + 1][0], sc[2 * kc + 1][1]);
            pa[3] = pack_bf16(sc[2 * kc + 1][2], sc[2 * kc + 1][3]);
            #pragma unroll
            for (int dp = 0; dp < 4; dp++) {
                int rowb = kc * 16 + (lane & 15);
                int colb = dp * 16 + (lane >> 4) * 8;
                uint32_t v0, v1, v2, v3;
                ldsm_x4_t(smem_u32(&Vs[rowb][colb]), v0, v1, v2, v3);
                mma16816(oacc[dp * 2 + 0], pa, v0, v1);
                mma16816(oacc[dp * 2 + 1], pa, v2, v3);
            }
        }
        if (kt + 2 < 16) loadKV((kt + 2) % 3, kt + 2);
    }

    l0 += __shfl_xor_sync(0xffffffffu, l0, 1);
    l0 += __shfl_xor_sync(0xffffffffu, l0, 2);
    l1 += __shfl_xor_sync(0xffffffffu, l1, 1);
    l1 += __shfl_xor_sync(0xffffffffu, l1, 2);

    const float gm = gamma[0];
    const float il0 = gm / l0, il1 = gm / l1;
    const int g = lane >> 2, q = lane & 3;
    const size_t row0 = (size_t)b * Mn + qt * 128 + qrow0 + g;
    const size_t row1 = row0 + 8;
    #pragma unroll
    for (int d = 0; d < 8; d++) {
        int col = h * DV + dvh * 64 + d * 8 + q * 2;
        float2 x0 = *(const float2*)(x + row0 * Cn + col);
        float2 x1 = *(const float2*)(x + row1 * Cn + col);
        float2 r0, r1;
        r0.x = oacc[d][0] * il0 + x0.x;
        r0.y = oacc[d][1] * il0 + x0.y;
        r1.x = oacc[d][2] * il1 + x1.x;
        r1.y = oacc[d][3] * il1 + x1.y;
        *(float2*)(out + row0 * Cn + col) = r0;
        *(float2*)(out + row1 * Cn + col) = r1;
    }
}

// ---------------- launch ----------------
extern "C" void kernel_launch(void* const* d_in, const int* in_sizes, int n_in,
                              void* d_out, int out_size)
{
    const float* x     = (const float*)d_in[0];
    const float* y     = (const float*)d_in[1];
    const float* Wq    = (const float*)d_in[2];
    const float* bq    = (const float*)d_in[3];
    const float* Wk    = (const float*)d_in[4];
    const float* bk    = (const float*)d_in[5];
    const float* Wv    = (const float*)d_in[6];
    const float* bv    = (const float*)d_in[7];
    const float* gamma = (const float*)d_in[8];
    float* out = (float*)d_out;

    cvt_all<<<4480, 256>>>(x, y, Wq, Wk, Wv);

    const int gemm_smem = 2 * 35840;   // 71,680 -> 2 CTAs/SM
    cudaFuncSetAttribute(gemm_fused, cudaFuncAttributeMaxDynamicSharedMemorySize, gemm_smem);
    gemm_fused<<<768, 256, gemm_smem>>>(bq, bk, bv);

    const int attn_smem = 40960 + 3 * 18432;  // 96,256 -> 2 CTAs/SM
    cudaFuncSetAttribute(attn_kernel, cudaFuncAttributeMaxDynamicSharedMemorySize, attn_smem);
    attn_kernel<<<dim3(16, 16, 4), 256, attn_smem>>>(x, gamma, out);
}